// round 2
// baseline (speedup 1.0000x reference)
#include <cuda_runtime.h>
#include <cuda_bf16.h>
#include <cstdint>

#define PROMPT_LEN 2048
#define VOCAB 49408
#define DIM 768
#define DIMK 2304          // 3 * DIM : [hi|lo|hi] x [hi|hi|lo] split-bf16 GEMM

#define BM 64
#define BN 128
#define BK 32
#define KSTRIDE 40   // BK + 8 bf16 pad -> 80B row stride, conflict-free & 16B aligned

// ---------------- scratch (no allocations allowed) ----------------
__device__ __nv_bfloat16 g_clip_bf[(size_t)VOCAB * DIMK];     // ~228 MB
__device__ __nv_bfloat16 g_prompt_bf[(size_t)PROMPT_LEN * DIMK];
__device__ float g_c_sq[VOCAB];
__device__ unsigned long long g_keys[PROMPT_LEN];

// ---------------- helpers ----------------
__device__ __forceinline__ unsigned f2ord(float f) {
    unsigned u = __float_as_uint(f);
    return (u & 0x80000000u) ? ~u : (u | 0x80000000u);
}

// ---------------- prep kernels ----------------
// clip layout per row (K=2304): [hi(768) | hi(768) | lo(768)]
__global__ void prep_clip_kernel(const float* __restrict__ clip) {
    int v = blockIdx.x;
    const float* row = clip + (size_t)v * DIM;
    __nv_bfloat16* dst = g_clip_bf + (size_t)v * DIMK;
    float ss = 0.f;
    #pragma unroll
    for (int i = 0; i < 3; i++) {
        int idx = threadIdx.x + i * 256;
        float x = row[idx];
        ss += x * x;
        __nv_bfloat16 hi = __float2bfloat16(x);
        __nv_bfloat16 lo = __float2bfloat16(x - __bfloat162float(hi));
        dst[idx] = hi;
        dst[idx + DIM] = hi;
        dst[idx + 2 * DIM] = lo;
    }
    #pragma unroll
    for (int off = 16; off > 0; off >>= 1)
        ss += __shfl_xor_sync(0xffffffffu, ss, off);
    __shared__ float warp_ss[8];
    int warp = threadIdx.x >> 5, lane = threadIdx.x & 31;
    if (lane == 0) warp_ss[warp] = ss;
    __syncthreads();
    if (threadIdx.x == 0) {
        float tot = 0.f;
        #pragma unroll
        for (int w = 0; w < 8; w++) tot += warp_ss[w];
        g_c_sq[v] = tot;
    }
}

// prompt layout per row (K=2304): [hi(768) | lo(768) | hi(768)]
__global__ void prep_prompt_kernel(const float* __restrict__ prompt) {
    int p = blockIdx.x;
    const float* row = prompt + (size_t)p * DIM;
    __nv_bfloat16* dst = g_prompt_bf + (size_t)p * DIMK;
    #pragma unroll
    for (int i = 0; i < 3; i++) {
        int idx = threadIdx.x + i * 256;
        float x = row[idx];
        __nv_bfloat16 hi = __float2bfloat16(x);
        __nv_bfloat16 lo = __float2bfloat16(x - __bfloat162float(hi));
        dst[idx] = hi;
        dst[idx + DIM] = lo;
        dst[idx + 2 * DIM] = hi;
    }
}

__global__ void init_keys_kernel() {
    int i = blockIdx.x * blockDim.x + threadIdx.x;
    if (i < PROMPT_LEN) g_keys[i] = 0xFFFFFFFFFFFFFFFFull;
}

// ---------------- fused split-bf16 mma GEMM + argmin ----------------
__global__ void __launch_bounds__(256, 2)
nn_kernel() {
    __shared__ __nv_bfloat16 a_sm[BM][KSTRIDE];
    __shared__ __nv_bfloat16 b_sm[BN][KSTRIDE];
    __shared__ unsigned long long key_sm[BM];

    const int ptile = blockIdx.x;   // fast dim: reuse clip tile across P-tiles in a wave
    const int vtile = blockIdx.y;
    const int t = threadIdx.x;
    const int warp = t >> 5, lane = t & 31;
    const int wm = warp & 1;        // 2 warps along M (32 rows each)
    const int wn = warp >> 1;       // 4 warps along N (32 cols each)
    const int g = lane >> 2;        // group id 0..7
    const int tid4 = lane & 3;

    const int p0 = ptile * BM;
    const int v0 = vtile * BN;

    if (t < BM) key_sm[t] = 0xFFFFFFFFFFFFFFFFull;

    float acc[2][4][4];
    #pragma unroll
    for (int mf = 0; mf < 2; mf++)
        #pragma unroll
        for (int nf = 0; nf < 4; nf++)
            #pragma unroll
            for (int j = 0; j < 4; j++) acc[mf][nf][j] = 0.f;

    const int lrow = t >> 2;        // 0..63
    const int lseg = t & 3;         // 0..3 (uint4 = 8 bf16)

    for (int k0 = 0; k0 < DIMK; k0 += BK) {
        __syncthreads();
        // A: 64x32 bf16 = 256 uint4, one per thread
        *(uint4*)&a_sm[lrow][lseg * 8] =
            *(const uint4*)&g_prompt_bf[(size_t)(p0 + lrow) * DIMK + k0 + lseg * 8];
        // B: 128x32 bf16 = 512 uint4, two per thread
        #pragma unroll
        for (int i = 0; i < 2; i++) {
            int brow = lrow + i * 64;
            *(uint4*)&b_sm[brow][lseg * 8] =
                *(const uint4*)&g_clip_bf[(size_t)(v0 + brow) * DIMK + k0 + lseg * 8];
        }
        __syncthreads();

        #pragma unroll
        for (int ks = 0; ks < 2; ks++) {  // two k=16 steps
            uint32_t a[2][4], b[4][2];
            const int kb = ks * 16 + 2 * tid4;
            #pragma unroll
            for (int mf = 0; mf < 2; mf++) {
                int r = wm * 32 + mf * 16 + g;
                a[mf][0] = *(const uint32_t*)&a_sm[r][kb];
                a[mf][1] = *(const uint32_t*)&a_sm[r + 8][kb];
                a[mf][2] = *(const uint32_t*)&a_sm[r][kb + 8];
                a[mf][3] = *(const uint32_t*)&a_sm[r + 8][kb + 8];
            }
            #pragma unroll
            for (int nf = 0; nf < 4; nf++) {
                int c = wn * 32 + nf * 8 + g;
                b[nf][0] = *(const uint32_t*)&b_sm[c][kb];
                b[nf][1] = *(const uint32_t*)&b_sm[c][kb + 8];
            }
            #pragma unroll
            for (int mf = 0; mf < 2; mf++)
                #pragma unroll
                for (int nf = 0; nf < 4; nf++) {
                    asm volatile(
                        "mma.sync.aligned.m16n8k16.row.col.f32.bf16.bf16.f32 "
                        "{%0,%1,%2,%3}, {%4,%5,%6,%7}, {%8,%9}, {%0,%1,%2,%3};\n"
                        : "+f"(acc[mf][nf][0]), "+f"(acc[mf][nf][1]),
                          "+f"(acc[mf][nf][2]), "+f"(acc[mf][nf][3])
                        : "r"(a[mf][0]), "r"(a[mf][1]), "r"(a[mf][2]), "r"(a[mf][3]),
                          "r"(b[nf][0]), "r"(b[nf][1]));
                }
        }
    }

    // epilogue: score = c_sq[col] - 2*cross ; per-row argmin
    #pragma unroll
    for (int mf = 0; mf < 2; mf++) {
        #pragma unroll
        for (int h = 0; h < 2; h++) {            // row g vs g+8
            int row = wm * 32 + mf * 16 + h * 8 + g;   // local row in tile
            float bv = 3.4e38f;
            int bi = 0;
            #pragma unroll
            for (int nf = 0; nf < 4; nf++) {
                #pragma unroll
                for (int j = 0; j < 2; j++) {
                    int col = v0 + wn * 32 + nf * 8 + 2 * tid4 + j;
                    float s = __ldg(&g_c_sq[col]) - 2.0f * acc[mf][nf][h * 2 + j];
                    if (s < bv) { bv = s; bi = col; }
                }
            }
            unsigned long long key =
                ((unsigned long long)f2ord(bv) << 32) | (unsigned)bi;
            #pragma unroll
            for (int off = 1; off < 4; off <<= 1) {
                unsigned long long other = __shfl_xor_sync(0xffffffffu, key, off);
                key = (other < key) ? other : key;
            }
            if (tid4 == 0) atomicMin(&key_sm[row], key);
        }
    }
    __syncthreads();
    if (t < BM) atomicMin(&g_keys[p0 + t], key_sm[t]);
}

// ---------------- gather output ----------------
__global__ void gather_kernel(const float* __restrict__ clip,
                              float* __restrict__ out, int write_ids) {
    int p = blockIdx.x;
    unsigned idx = (unsigned)(g_keys[p] & 0xFFFFFFFFu);
    const float* src = clip + (size_t)idx * DIM;
    float* dst = out + (size_t)p * DIM;
    for (int i = threadIdx.x; i < DIM; i += blockDim.x) dst[i] = src[i];
    if (threadIdx.x == 0 && write_ids)
        out[(size_t)PROMPT_LEN * DIM + p] = (float)idx;
}

// ---------------- launch ----------------
extern "C" void kernel_launch(void* const* d_in, const int* in_sizes, int n_in,
                              void* d_out, int out_size) {
    const float* prompt = (const float*)d_in[0];   // (2048, 768) fp32
    const float* clip   = (const float*)d_in[1];   // (49408, 768) fp32
    float* out = (float*)d_out;

    prep_clip_kernel<<<VOCAB, 256>>>(clip);
    prep_prompt_kernel<<<PROMPT_LEN, 256>>>(prompt);
    init_keys_kernel<<<(PROMPT_LEN + 255) / 256, 256>>>();

    dim3 grid(PROMPT_LEN / BM, VOCAB / BN);   // (32, 386); x fast -> clip tile reuse in L2
    nn_kernel<<<grid, 256>>>();

    int write_ids = (out_size >= PROMPT_LEN * DIM + PROMPT_LEN) ? 1 : 0;
    gather_kernel<<<PROMPT_LEN, 128>>>(clip, out, write_ids);
}

// round 5
// speedup vs baseline: 4.8488x; 4.8488x over previous
#include <cuda_runtime.h>
#include <cuda_bf16.h>
#include <cstdint>

#define PROMPT_LEN 2048
#define VOCAB 49408
#define DIM 768

#define BM 128
#define BN 128
#define BK 64
#define NCHUNK (DIM / BK)       // 12
#define STAGES 3
#define ASTAGE_BYTES (BM * 128)                 // 16 KB (128 rows x 128B)
#define STAGE_BYTES (2 * ASTAGE_BYTES)          // 32 KB (A + B)
#define RM_OFF (STAGES * STAGE_BYTES)           // 98304
#define SMEM_TOTAL (RM_OFF + 1024)              // 99328

#define NVT (VOCAB / BN)        // 386 vtiles
#define EPS 0.3f
#define CAND_CAP (8u * 1024u * 1024u)

// ---------------- scratch (no allocations allowed) ----------------
__device__ __nv_bfloat16 g_clip_bf[(size_t)VOCAB * DIM];       // 76 MB
__device__ __nv_bfloat16 g_prompt_bf[(size_t)PROMPT_LEN * DIM];
__device__ float g_c_sq[VOCAB];
__device__ unsigned g_ctamin[(size_t)NVT * PROMPT_LEN];        // per-vtile row mins (ordered uint)
__device__ unsigned g_rowmin[PROMPT_LEN];                      // global approx min (ordered uint)
__device__ unsigned long long g_keys2[PROMPT_LEN];             // exact (q<<16)|col
__device__ unsigned g_cand_count;
__device__ float4 g_cand[CAND_CAP];                            // {score, row, col, -}

// ---------------- helpers ----------------
__device__ __forceinline__ uint32_t smem_u32(const void* p) {
    uint32_t a;
    asm("{ .reg .u64 t; cvta.to.shared.u64 t, %1; cvt.u32.u64 %0, t; }" : "=r"(a) : "l"(p));
    return a;
}
__device__ __forceinline__ unsigned f2ord(float f) {
    unsigned u = __float_as_uint(f);
    return (u & 0x80000000u) ? ~u : (u | 0x80000000u);
}
__device__ __forceinline__ float ord2f(unsigned k) {
    unsigned u = (k & 0x80000000u) ? (k & 0x7FFFFFFFu) : ~k;
    return __uint_as_float(u);
}
__device__ __forceinline__ void cp16(uint32_t saddr, const void* g) {
    asm volatile("cp.async.cg.shared.global [%0], [%1], 16;" :: "r"(saddr), "l"(g));
}
#define CP_COMMIT() asm volatile("cp.async.commit_group;" ::: "memory")
#define CP_WAIT1()  asm volatile("cp.async.wait_group 1;" ::: "memory")

__device__ __forceinline__ void ldsm4(uint32_t* r, uint32_t a) {
    asm volatile("ldmatrix.sync.aligned.m8n8.x4.shared.b16 {%0,%1,%2,%3}, [%4];"
                 : "=r"(r[0]), "=r"(r[1]), "=r"(r[2]), "=r"(r[3]) : "r"(a));
}
__device__ __forceinline__ void mma16816(float* c, const uint32_t* a, uint32_t b0, uint32_t b1) {
    asm volatile(
        "mma.sync.aligned.m16n8k16.row.col.f32.bf16.bf16.f32 "
        "{%0,%1,%2,%3}, {%4,%5,%6,%7}, {%8,%9}, {%0,%1,%2,%3};\n"
        : "+f"(c[0]), "+f"(c[1]), "+f"(c[2]), "+f"(c[3])
        : "r"(a[0]), "r"(a[1]), "r"(a[2]), "r"(a[3]), "r"(b0), "r"(b1));
}

// ---------------- prep ----------------
__global__ void prep_clip_kernel(const float* __restrict__ clip) {
    int v = blockIdx.x;
    const float* row = clip + (size_t)v * DIM;
    __nv_bfloat16* dst = g_clip_bf + (size_t)v * DIM;
    float ss = 0.f;
    #pragma unroll
    for (int i = 0; i < 3; i++) {
        int idx = threadIdx.x + i * 256;
        float x = row[idx];
        ss += x * x;
        dst[idx] = __float2bfloat16(x);
    }
    #pragma unroll
    for (int off = 16; off > 0; off >>= 1)
        ss += __shfl_xor_sync(0xffffffffu, ss, off);
    __shared__ float warp_ss[8];
    int warp = threadIdx.x >> 5, lane = threadIdx.x & 31;
    if (lane == 0) warp_ss[warp] = ss;
    __syncthreads();
    if (threadIdx.x == 0) {
        float tot = 0.f;
        #pragma unroll
        for (int w = 0; w < 8; w++) tot += warp_ss[w];
        g_c_sq[v] = tot;
    }
}

__global__ void prep_prompt_kernel(const float* __restrict__ prompt) {
    int p = blockIdx.x;
    const float* row = prompt + (size_t)p * DIM;
    __nv_bfloat16* dst = g_prompt_bf + (size_t)p * DIM;
    #pragma unroll
    for (int i = 0; i < 3; i++) {
        int idx = threadIdx.x + i * 256;
        dst[idx] = __float2bfloat16(row[idx]);
    }
}

__global__ void init_kernel() {
    int i = blockIdx.x * blockDim.x + threadIdx.x;
    if (i < PROMPT_LEN) g_keys2[i] = 0xFFFFFFFFFFFFFFFFull;
    if (i == 0) g_cand_count = 0u;
}

// ---------------- Pass A: pipelined bf16 GEMM + candidate extraction -----
__global__ void __launch_bounds__(256, 2)
nn_kernel() {
    extern __shared__ __align__(1024) char smem[];
    const uint32_t sb = smem_u32(smem);
    const int tid = threadIdx.x;
    const int wid = tid >> 5, lane = tid & 31;
    const int wm = wid & 1, wn = wid >> 1;
    const int g = lane >> 2, tid4 = lane & 3;
    const int j = lane & 7, sel = lane >> 3;
    const int p0 = blockIdx.x * BM;
    const int v0 = blockIdx.y * BN;

    float acc[4][4][4];
    #pragma unroll
    for (int m = 0; m < 4; m++)
        #pragma unroll
        for (int n = 0; n < 4; n++)
            #pragma unroll
            for (int q = 0; q < 4; q++) acc[m][n][q] = 0.f;

    auto issue = [&](int c, int s) {
        uint32_t base = sb + s * STAGE_BYTES;
        #pragma unroll
        for (int t = 0; t < 4; t++) {
            int e = tid + t * 256;
            int row = e >> 3, ch = e & 7;
            uint32_t off = (uint32_t)row * 128u + (uint32_t)((ch * 16) ^ ((row & 7) << 4));
            cp16(base + off, g_prompt_bf + (size_t)(p0 + row) * DIM + c * BK + ch * 8);
            cp16(base + ASTAGE_BYTES + off, g_clip_bf + (size_t)(v0 + row) * DIM + c * BK + ch * 8);
        }
    };

    issue(0, 0); CP_COMMIT();
    issue(1, 1); CP_COMMIT();

    // precomputed lane address components
    const uint32_t a_row = (uint32_t)(j + 8 * (sel & 1)) * 128u;
    const uint32_t b_row = (uint32_t)(j + 8 * (sel >> 1)) * 128u;
    const uint32_t a_c16 = 16u * (uint32_t)(sel >> 1);
    const uint32_t b_c16 = 16u * (uint32_t)(sel & 1);
    const uint32_t xorm = (uint32_t)j << 4;

    for (int c = 0; c < NCHUNK; c++) {
        CP_WAIT1();
        __syncthreads();
        if (c + 2 < NCHUNK) issue(c + 2, (c + 2) % 3);
        CP_COMMIT();

        const uint32_t stA = sb + (uint32_t)(c % 3) * STAGE_BYTES;
        const uint32_t stB = stA + ASTAGE_BYTES;
        #pragma unroll
        for (int ks = 0; ks < 4; ks++) {
            const uint32_t KB = (uint32_t)ks * 32u;
            uint32_t a[4][4], b[2][4];
            #pragma unroll
            for (int mf = 0; mf < 4; mf++) {
                uint32_t addr = stA + (uint32_t)(wm * 64 + mf * 16) * 128u + a_row
                              + ((KB + a_c16) ^ xorm);
                ldsm4(a[mf], addr);
            }
            #pragma unroll
            for (int nf2 = 0; nf2 < 2; nf2++) {
                uint32_t addr = stB + (uint32_t)(wn * 32 + nf2 * 16) * 128u + b_row
                              + ((KB + b_c16) ^ xorm);
                ldsm4(b[nf2], addr);
            }
            #pragma unroll
            for (int mf = 0; mf < 4; mf++)
                #pragma unroll
                for (int nf = 0; nf < 4; nf++)
                    mma16816(acc[mf][nf], a[mf], b[nf >> 1][2 * (nf & 1)],
                             b[nf >> 1][2 * (nf & 1) + 1]);
        }
    }

    // ---------------- epilogue ----------------
    unsigned* rowmin = (unsigned*)(smem + RM_OFF);       // 128 uints
    unsigned* s_cnt  = (unsigned*)(smem + RM_OFF + 512);
    unsigned* s_base = (unsigned*)(smem + RM_OFF + 516);
    float4* staging  = (float4*)smem;                    // reuse pipeline smem (64 KB max)

    if (tid < BM) rowmin[tid] = 0xFFFFFFFFu;
    if (tid == 0) *s_cnt = 0u;
    __syncthreads();   // also: all warps done with mainloop smem

    float cs[8];
    #pragma unroll
    for (int nf = 0; nf < 4; nf++)
        #pragma unroll
        for (int jj = 0; jj < 2; jj++)
            cs[nf * 2 + jj] = __ldg(&g_c_sq[v0 + wn * 32 + nf * 8 + 2 * tid4 + jj]);

    // CTA per-row min
    #pragma unroll
    for (int mf = 0; mf < 4; mf++)
        #pragma unroll
        for (int h = 0; h < 2; h++) {
            int lr = wm * 64 + mf * 16 + h * 8 + g;
            float best = 3.4e38f;
            #pragma unroll
            for (int nf = 0; nf < 4; nf++)
                #pragma unroll
                for (int jj = 0; jj < 2; jj++) {
                    float s = cs[nf * 2 + jj] - 2.0f * acc[mf][nf][h * 2 + jj];
                    best = fminf(best, s);
                }
            atomicMin(&rowmin[lr], f2ord(best));
        }
    __syncthreads();

    // push candidates within EPS of CTA row-min into smem staging
    #pragma unroll
    for (int mf = 0; mf < 4; mf++)
        #pragma unroll
        for (int h = 0; h < 2; h++) {
            int lr = wm * 64 + mf * 16 + h * 8 + g;
            float thr = ord2f(rowmin[lr]) + EPS;
            #pragma unroll
            for (int nf = 0; nf < 4; nf++)
                #pragma unroll
                for (int jj = 0; jj < 2; jj++) {
                    float s = cs[nf * 2 + jj] - 2.0f * acc[mf][nf][h * 2 + jj];
                    if (s <= thr) {
                        unsigned slot = atomicAdd(s_cnt, 1u);  // bounded by 4096 = 256*16
                        staging[slot] = make_float4(
                            s, __uint_as_float((unsigned)(p0 + lr)),
                            __uint_as_float((unsigned)(v0 + wn * 32 + nf * 8 + 2 * tid4 + jj)),
                            0.f);
                    }
                }
        }
    __syncthreads();
    if (tid == 0) *s_base = atomicAdd(&g_cand_count, *s_cnt);
    // per-vtile row mins (dense, no atomics)
    if (tid < BM)
        g_ctamin[(size_t)blockIdx.y * PROMPT_LEN + p0 + tid] = rowmin[tid];
    __syncthreads();
    unsigned cnt = *s_cnt, base = *s_base;
    for (unsigned i = tid; i < cnt; i += 256)
        if (base + i < CAND_CAP) g_cand[base + i] = staging[i];
}

// ---------------- global row-min reduce ----------------
__global__ void reduce_min_kernel() {
    int r = blockIdx.x;
    unsigned m = 0xFFFFFFFFu;
    for (int v = threadIdx.x; v < NVT; v += 128)
        m = min(m, g_ctamin[(size_t)v * PROMPT_LEN + r]);
    #pragma unroll
    for (int off = 16; off > 0; off >>= 1)
        m = min(m, __shfl_xor_sync(0xffffffffu, m, off));
    __shared__ unsigned wmin[4];
    if ((threadIdx.x & 31) == 0) wmin[threadIdx.x >> 5] = m;
    __syncthreads();
    if (threadIdx.x == 0) {
        m = min(min(wmin[0], wmin[1]), min(wmin[2], wmin[3]));
        g_rowmin[r] = m;
    }
}

// ---------------- Pass B: exact rescore of surviving candidates ----------
__global__ void rescore_kernel(const float* __restrict__ prompt,
                               const float* __restrict__ clip) {
    unsigned n = g_cand_count;
    if (n > CAND_CAP) n = CAND_CAP;
    int lane = threadIdx.x & 31;
    unsigned gw = (blockIdx.x * blockDim.x + threadIdx.x) >> 5;
    unsigned nw = (gridDim.x * blockDim.x) >> 5;
    for (unsigned i = gw; i < n; i += nw) {
        float4 cand = g_cand[i];
        float s = cand.x;
        unsigned row = __float_as_uint(cand.y);
        unsigned col = __float_as_uint(cand.z);
        float minf = ord2f(g_rowmin[row]);
        if (s <= minf + EPS) {
            const float* p = prompt + (size_t)row * DIM;
            const float* c = clip + (size_t)col * DIM;
            double d2 = 0.0;
            for (int k = lane; k < DIM; k += 32) {
                double d = (double)p[k] - (double)c[k];
                d2 += d * d;
            }
            #pragma unroll
            for (int off = 16; off > 0; off >>= 1)
                d2 += __shfl_xor_sync(0xffffffffu, d2, off);
            if (lane == 0) {
                unsigned long long q = (unsigned long long)llround(d2 * 1048576.0);
                atomicMin(&g_keys2[row], (q << 16) | (unsigned long long)col);
            }
        }
    }
}

// ---------------- gather ----------------
__global__ void gather_kernel(const float* __restrict__ clip,
                              float* __restrict__ out, int write_ids) {
    int p = blockIdx.x;
    unsigned idx = (unsigned)(g_keys2[p] & 0xFFFFull);
    const float* src = clip + (size_t)idx * DIM;
    float* dst = out + (size_t)p * DIM;
    for (int i = threadIdx.x; i < DIM; i += blockDim.x) dst[i] = src[i];
    if (threadIdx.x == 0 && write_ids)
        out[(size_t)PROMPT_LEN * DIM + p] = (float)idx;
}

// ---------------- launch ----------------
extern "C" void kernel_launch(void* const* d_in, const int* in_sizes, int n_in,
                              void* d_out, int out_size) {
    const float* prompt = (const float*)d_in[0];   // (2048, 768) fp32
    const float* clip   = (const float*)d_in[1];   // (49408, 768) fp32
    float* out = (float*)d_out;

    cudaFuncSetAttribute(nn_kernel, cudaFuncAttributeMaxDynamicSharedMemorySize,
                         SMEM_TOTAL);

    prep_clip_kernel<<<VOCAB, 256>>>(clip);
    prep_prompt_kernel<<<PROMPT_LEN, 256>>>(prompt);
    init_kernel<<<(PROMPT_LEN + 255) / 256, 256>>>();

    dim3 grid(PROMPT_LEN / BM, NVT);   // (16, 386); x fast -> clip tile reuse in L2
    nn_kernel<<<grid, 256, SMEM_TOTAL>>>();

    reduce_min_kernel<<<PROMPT_LEN, 128>>>();
    rescore_kernel<<<512, 256>>>(prompt, clip);

    int write_ids = (out_size >= PROMPT_LEN * DIM + PROMPT_LEN) ? 1 : 0;
    gather_kernel<<<PROMPT_LEN, 128>>>(clip, out, write_ids);
}